// round 7
// baseline (speedup 1.0000x reference)
#include <cuda_runtime.h>
#include <cuda_bf16.h>
#include <math_constants.h>
#include <cstdint>

#define NNODES 8192
#define FIN    512
#define FOUT   256
#define NEG_SLOPE 0.2f

#define BM 64
#define BK 64
#define NCHUNK (NNODES / BK)     // 128
#define ATTN_THREADS 768         // 16 MMA warps + 8 producer warps

// ---------------- device scratch ----------------
__device__ float         g_H [NNODES * FOUT];
__device__ __nv_bfloat16 g_HT[FOUT * NNODES];
__device__ float         g_s [NNODES];
__device__ float         g_t [NNODES];

// ---------------- helpers (base PTX, sm_80-compatible) ----------------
static __device__ __forceinline__ uint32_t smem_u32(const void* p) {
    uint32_t a;
    asm("{ .reg .u64 t; cvta.to.shared.u64 t, %1; cvt.u32.u64 %0, t; }" : "=r"(a) : "l"(p));
    return a;
}
static __device__ __forceinline__ void cp_async16(uint32_t dst, const void* src) {
    asm volatile("cp.async.cg.shared.global [%0], [%1], 16;" :: "r"(dst), "l"(src));
}
static __device__ __forceinline__ void cp_commit() {
    asm volatile("cp.async.commit_group;" ::: "memory");
}
static __device__ __forceinline__ void cp_wait_all() {
    asm volatile("cp.async.wait_group 0;" ::: "memory");
}
static __device__ __forceinline__ void ldm_x4(uint32_t& r0, uint32_t& r1,
                                              uint32_t& r2, uint32_t& r3, uint32_t addr) {
    asm volatile("ldmatrix.sync.aligned.m8n8.x4.shared.b16 {%0, %1, %2, %3}, [%4];"
                 : "=r"(r0), "=r"(r1), "=r"(r2), "=r"(r3) : "r"(addr));
}
static __device__ __forceinline__ void mma_16816(float* d, const uint32_t* a, const uint32_t* b) {
    asm volatile(
        "mma.sync.aligned.m16n8k16.row.col.f32.bf16.bf16.f32 "
        "{%0, %1, %2, %3}, {%4, %5, %6, %7}, {%8, %9}, {%0, %1, %2, %3};"
        : "+f"(d[0]), "+f"(d[1]), "+f"(d[2]), "+f"(d[3])
        : "r"(a[0]), "r"(a[1]), "r"(a[2]), "r"(a[3]), "r"(b[0]), "r"(b[1]));
}
static __device__ __forceinline__ void mma_tf32(float* d, const uint32_t* a, const uint32_t* b) {
    asm volatile(
        "mma.sync.aligned.m16n8k8.row.col.f32.tf32.tf32.f32 "
        "{%0, %1, %2, %3}, {%4, %5, %6, %7}, {%8, %9}, {%0, %1, %2, %3};"
        : "+f"(d[0]), "+f"(d[1]), "+f"(d[2]), "+f"(d[3])
        : "r"(a[0]), "r"(a[1]), "r"(a[2]), "r"(a[3]), "r"(b[0]), "r"(b[1]));
}
static __device__ __forceinline__ uint32_t f2tf32(float v) {
    uint32_t r;
    asm("cvt.rna.tf32.f32 %0, %1;" : "=r"(r) : "f"(v));
    return r;
}
static __device__ __forceinline__ uint32_t sw128(uint32_t b) { return b ^ ((b >> 3) & 0x70); }

// ---------------- Kernel 1: H = X @ W^T via tf32 mma ----------------
#define GPITCH 36
#define XS_OFF0 0u
#define XS_OFF1 18432u
#define WS_OFF0 36864u
#define WS_OFF1 46080u
#define GEMM_SMEM 55296

__global__ void __launch_bounds__(256)
gemm_H_tf32_kernel(const float* __restrict__ X, const float* __restrict__ W) {
    extern __shared__ char gsm[];
    const uint32_t base = smem_u32(gsm);
    float* sm = (float*)gsm;

    const int tid = threadIdx.x;
    const int lane = tid & 31;
    const int wid = tid >> 5;
    const int wm = (wid & 3) * 32;
    const int wn = (wid >> 2) * 32;
    const int row0 = blockIdx.x * 128;
    const int col0 = blockIdx.y * 64;

    float acc[2][4][4];
#pragma unroll
    for (int mt = 0; mt < 2; mt++)
#pragma unroll
        for (int nt = 0; nt < 4; nt++)
#pragma unroll
            for (int e = 0; e < 4; e++) acc[mt][nt][e] = 0.f;

#pragma unroll
    for (int q = 0; q < 4; q++) {
        int id = tid + q * 256;
        int r = id >> 3, kq = id & 7;
        cp_async16(base + XS_OFF0 + (uint32_t)(r * GPITCH + kq * 4) * 4u,
                   X + (size_t)(row0 + r) * FIN + kq * 4);
    }
#pragma unroll
    for (int q = 0; q < 2; q++) {
        int id = tid + q * 256;
        int r = id >> 3, kq = id & 7;
        cp_async16(base + WS_OFF0 + (uint32_t)(r * GPITCH + kq * 4) * 4u,
                   W + (size_t)(col0 + r) * FIN + kq * 4);
    }
    cp_commit();

    const int a_r = lane >> 2;
    const int a_k = lane & 3;

#pragma unroll 1
    for (int kb = 0; kb < FIN / 32; kb++) {
        const int buf = kb & 1;
        const uint32_t xs = buf ? XS_OFF1 : XS_OFF0;
        const uint32_t ws = buf ? WS_OFF1 : WS_OFF0;
        cp_wait_all();
        __syncthreads();

        if (kb + 1 < FIN / 32) {
            const uint32_t xsn = buf ? XS_OFF0 : XS_OFF1;
            const uint32_t wsn = buf ? WS_OFF0 : WS_OFF1;
            const int k0n = (kb + 1) * 32;
#pragma unroll
            for (int q = 0; q < 4; q++) {
                int id = tid + q * 256;
                int r = id >> 3, kq = id & 7;
                cp_async16(base + xsn + (uint32_t)(r * GPITCH + kq * 4) * 4u,
                           X + (size_t)(row0 + r) * FIN + k0n + kq * 4);
            }
#pragma unroll
            for (int q = 0; q < 2; q++) {
                int id = tid + q * 256;
                int r = id >> 3, kq = id & 7;
                cp_async16(base + wsn + (uint32_t)(r * GPITCH + kq * 4) * 4u,
                           W + (size_t)(col0 + r) * FIN + k0n + kq * 4);
            }
            cp_commit();
        }

        const float* Xs = (const float*)((const char*)sm + xs);
        const float* Ws = (const float*)((const char*)sm + ws);
#pragma unroll
        for (int kk = 0; kk < 32; kk += 8) {
            uint32_t a[2][4];
#pragma unroll
            for (int mt = 0; mt < 2; mt++) {
                const int m = wm + mt * 16 + a_r;
                a[mt][0] = f2tf32(Xs[m * GPITCH + kk + a_k]);
                a[mt][1] = f2tf32(Xs[(m + 8) * GPITCH + kk + a_k]);
                a[mt][2] = f2tf32(Xs[m * GPITCH + kk + a_k + 4]);
                a[mt][3] = f2tf32(Xs[(m + 8) * GPITCH + kk + a_k + 4]);
            }
            uint32_t b[4][2];
#pragma unroll
            for (int nt = 0; nt < 4; nt++) {
                const int n = wn + nt * 8 + a_r;
                b[nt][0] = f2tf32(Ws[n * GPITCH + kk + a_k]);
                b[nt][1] = f2tf32(Ws[n * GPITCH + kk + a_k + 4]);
            }
#pragma unroll
            for (int mt = 0; mt < 2; mt++)
#pragma unroll
                for (int nt = 0; nt < 4; nt++)
                    mma_tf32(acc[mt][nt], a[mt], b[nt]);
        }
    }

#pragma unroll
    for (int mt = 0; mt < 2; mt++) {
#pragma unroll
        for (int nt = 0; nt < 4; nt++) {
#pragma unroll
            for (int half = 0; half < 2; half++) {
                const int row = row0 + wm + mt * 16 + (lane >> 2) + half * 8;
                const int col = col0 + wn + nt * 8 + (lane & 3) * 2;
                float v0 = acc[mt][nt][2 * half];
                float v1 = acc[mt][nt][2 * half + 1];
                *reinterpret_cast<float2*>(g_H + (size_t)row * FOUT + col) = make_float2(v0, v1);
                g_HT[(size_t)col * NNODES + row]       = __float2bfloat16(v0);
                g_HT[(size_t)(col + 1) * NNODES + row] = __float2bfloat16(v1);
            }
        }
    }
}

// ---------------- Kernel 2: s = H a_l, t = H a_r ----------------
__global__ void st_kernel(const float* __restrict__ attn_w) {
    const int lane = threadIdx.x & 31;
    const int warp = threadIdx.x >> 5;
    const int row = blockIdx.x * 8 + warp;
    float s = 0.f, t = 0.f;
#pragma unroll
    for (int o = lane; o < FOUT; o += 32) {
        float h = g_H[(size_t)row * FOUT + o];
        s += h * attn_w[o];
        t += h * attn_w[FOUT + o];
    }
#pragma unroll
    for (int off = 16; off; off >>= 1) {
        s += __shfl_down_sync(0xffffffffu, s, off);
        t += __shfl_down_sync(0xffffffffu, t, off);
    }
    if (lane == 0) { g_s[row] = s; g_t[row] = t; }
}

// ---------------- Kernel 3: warp-specialized flash attention ----------------
// 24 warps: wid 0..15 = MMA (tile 32x32), wid 16..23 = producers (P, Hs, M, rowsum)
#define PS_OFF0 0u
#define PS_OFF1 8192u
#define HS_OFF0 16384u
#define HS_OFF1 49152u
#define RS_OFF  81920u
#define SMEM_DYN 83456

__global__ void __launch_bounds__(ATTN_THREADS, 1)
attn_mma_kernel(const float* __restrict__ M, float* __restrict__ out) {
    extern __shared__ char dsm[];
    const uint32_t raw = smem_u32(dsm);
    const uint32_t base = (raw + 1023u) & ~1023u;
    char* al = dsm + (base - raw);

    const int tid  = threadIdx.x;
    const int lane = tid & 31;
    const int wid  = tid >> 5;
    const int row0 = blockIdx.x * BM;

    float* rowsum = (float*)(al + RS_OFF);

    const bool is_producer = (wid >= 16);

    if (is_producer) {
        // ============== PRODUCER PATH ==============
        const int ptid = tid - 512;                 // 0..255
        const int pr_r   = ptid >> 2;               // row 0..63
        const int pr_seg = ptid & 3;                // 16 cols at seg*16
        const float si = g_s[row0 + pr_r];
        const float* Mrow = M + (size_t)(row0 + pr_r) * NNODES + pr_seg * 16;
        const float* Trow = g_t + pr_seg * 16;
        float rs_reg = 0.f;

        // prologue: Hs(0)
#pragma unroll
        for (int q = 0; q < 8; q++) {
            int id = ptid + q * 256;                // 0..2047 uint4
            int n = id >> 3, kq = id & 7;
            cp_async16(base + HS_OFF0 + sw128((uint32_t)n * 128u + (uint32_t)kq * 16u),
                       g_HT + (size_t)n * NNODES + kq * 8);
        }
        cp_commit();

        // P(0) synchronous
#pragma unroll
        for (int j = 0; j < 4; j++) {
            const float4 m4 = *reinterpret_cast<const float4*>(Mrow + j * 4);
            const float4 t4 = *reinterpret_cast<const float4*>(Trow + j * 4);
            float pr[4];
#pragma unroll
            for (int e = 0; e < 4; e++) {
                float m = (&m4.x)[e];
                float v = si + (&t4.x)[e];
                float lr = fmaxf(v, NEG_SLOPE * v);
                float pv = (m > 0.f) ? __expf(m * lr) : 0.f;
                pr[e] = __bfloat162float(__float2bfloat16(pv));
            }
            __nv_bfloat162 p01 = __floats2bfloat162_rn(pr[0], pr[1]);
            __nv_bfloat162 p23 = __floats2bfloat162_rn(pr[2], pr[3]);
            uint2 packed;
            packed.x = *reinterpret_cast<uint32_t*>(&p01);
            packed.y = *reinterpret_cast<uint32_t*>(&p23);
            uint32_t byte = (uint32_t)pr_r * 128u + (uint32_t)(pr_seg * 16 + j * 4) * 2u;
            *reinterpret_cast<uint2*>(al + PS_OFF0 + sw128(byte)) = packed;
            rs_reg += pr[0] + pr[1] + pr[2] + pr[3];
        }

        // M(1) prefetch
        float4 mcur[4];
#pragma unroll
        for (int j = 0; j < 4; j++)
            mcur[j] = *reinterpret_cast<const float4*>(Mrow + BK + j * 4);

#pragma unroll 1
        for (int c = 0; c < NCHUNK; ++c) {
            const int buf = c & 1;
            cp_wait_all();
            __syncthreads();

            const int cn = c + 1;
            if (cn < NCHUNK) {
                const uint32_t hs_nxt = buf ? HS_OFF0 : HS_OFF1;
                const uint32_t ps_nxt = buf ? PS_OFF0 : PS_OFF1;
#pragma unroll
                for (int q = 0; q < 8; q++) {
                    int id = ptid + q * 256;
                    int n = id >> 3, kq = id & 7;
                    cp_async16(base + hs_nxt + sw128((uint32_t)n * 128u + (uint32_t)kq * 16u),
                               g_HT + (size_t)n * NNODES + cn * BK + kq * 8);
                }
                cp_commit();

                float4 mnext[4];
                if (c + 2 < NCHUNK) {
#pragma unroll
                    for (int j = 0; j < 4; j++)
                        mnext[j] = *reinterpret_cast<const float4*>(Mrow + (c + 2) * BK + j * 4);
                }

                // P(c+1)
#pragma unroll
                for (int j = 0; j < 4; j++) {
                    const float4 t4 = *reinterpret_cast<const float4*>(Trow + cn * BK + j * 4);
                    float pr[4];
#pragma unroll
                    for (int e = 0; e < 4; e++) {
                        float m = (&mcur[j].x)[e];
                        float v = si + (&t4.x)[e];
                        float lr = fmaxf(v, NEG_SLOPE * v);
                        float pv = (m > 0.f) ? __expf(m * lr) : 0.f;
                        pr[e] = __bfloat162float(__float2bfloat16(pv));
                    }
                    __nv_bfloat162 p01 = __floats2bfloat162_rn(pr[0], pr[1]);
                    __nv_bfloat162 p23 = __floats2bfloat162_rn(pr[2], pr[3]);
                    uint2 packed;
                    packed.x = *reinterpret_cast<uint32_t*>(&p01);
                    packed.y = *reinterpret_cast<uint32_t*>(&p23);
                    uint32_t byte = (uint32_t)pr_r * 128u + (uint32_t)(pr_seg * 16 + j * 4) * 2u;
                    *reinterpret_cast<uint2*>(al + ps_nxt + sw128(byte)) = packed;
                    rs_reg += pr[0] + pr[1] + pr[2] + pr[3];
                }
#pragma unroll
                for (int j = 0; j < 4; j++) mcur[j] = mnext[j];
            }
        }

        // rowsum: reduce 4 threads of a row
        rs_reg += __shfl_xor_sync(0xffffffffu, rs_reg, 1);
        rs_reg += __shfl_xor_sync(0xffffffffu, rs_reg, 2);
        if ((ptid & 3) == 0) rowsum[pr_r] = rs_reg;
        __syncthreads();
        // producers done (no epilogue work)
    } else {
        // ============== MMA PATH ==============
        const int mrow0 = (wid & 1) * 32;
        const int ncol0 = (wid >> 1) * 32;

        float acc[2][4][4];
#pragma unroll
        for (int mt = 0; mt < 2; mt++)
#pragma unroll
            for (int nt = 0; nt < 4; nt++)
#pragma unroll
                for (int e = 0; e < 4; e++) acc[mt][nt][e] = 0.f;

#pragma unroll 1
        for (int c = 0; c < NCHUNK; ++c) {
            const int buf = c & 1;
            const uint32_t ps_off = buf ? PS_OFF1 : PS_OFF0;
            const uint32_t hs_off = buf ? HS_OFF1 : HS_OFF0;

            cp_wait_all();        // no groups on this thread: no-op
            __syncthreads();

#pragma unroll
            for (int ks = 0; ks < 4; ks++) {
                const uint32_t kb = (uint32_t)(ks * 16 + (lane >> 4) * 8) * 2u;
                uint32_t a[2][4];
#pragma unroll
                for (int mt = 0; mt < 2; mt++) {
                    uint32_t addr = base + ps_off +
                        sw128((uint32_t)(mrow0 + mt * 16 + (lane & 15)) * 128u + kb);
                    ldm_x4(a[mt][0], a[mt][1], a[mt][2], a[mt][3], addr);
                }
                uint32_t b[4][2];
#pragma unroll
                for (int np = 0; np < 2; np++) {
                    uint32_t r0, r1, r2, r3;
                    uint32_t addr = base + hs_off +
                        sw128((uint32_t)(ncol0 + np * 16 + (lane & 15)) * 128u + kb);
                    ldm_x4(r0, r1, r2, r3, addr);
                    b[2 * np][0] = r0; b[2 * np][1] = r2;
                    b[2 * np + 1][0] = r1; b[2 * np + 1][1] = r3;
                }
#pragma unroll
                for (int mt = 0; mt < 2; mt++)
#pragma unroll
                    for (int nt = 0; nt < 4; nt++)
                        mma_16816(acc[mt][nt], a[mt], b[nt]);
            }
        }

        __syncthreads();   // rowsum ready

        // epilogue: warp tile 32x32
#pragma unroll
        for (int mt = 0; mt < 2; mt++) {
#pragma unroll
            for (int half = 0; half < 2; half++) {
                const int rl = mrow0 + mt * 16 + (lane >> 2) + half * 8;
                const int row = row0 + rl;
                const float rs = rowsum[rl];
                const bool nb = !(rs > 0.f);
                const float inv = nb ? 0.f : 1.f / rs;
#pragma unroll
                for (int nt = 0; nt < 4; nt++) {
                    const int col = ncol0 + nt * 8 + (lane & 3) * 2;
                    float u0 = acc[mt][nt][2 * half]     * inv;
                    float u1 = acc[mt][nt][2 * half + 1] * inv;
                    if (nb) {
                        u0 = g_H[(size_t)row * FOUT + col];
                        u1 = g_H[(size_t)row * FOUT + col + 1];
                    }
                    float2 z;
                    z.x = 1.f / (1.f + __expf(-u0));
                    z.y = 1.f / (1.f + __expf(-u1));
                    *reinterpret_cast<float2*>(out + (size_t)row * FOUT + col) = z;
                }
            }
        }
    }
}

// ---------------- launch ----------------
extern "C" void kernel_launch(void* const* d_in, const int* in_sizes, int n_in,
                              void* d_out, int out_size) {
    const float *X = nullptr, *M = nullptr, *W = nullptr, *AW = nullptr;
    for (int i = 0; i < n_in; i++) {
        switch (in_sizes[i]) {
            case NNODES * FIN:    X  = (const float*)d_in[i]; break;
            case NNODES * NNODES: M  = (const float*)d_in[i]; break;
            case FOUT * FIN:      W  = (const float*)d_in[i]; break;
            case 2 * FOUT:        AW = (const float*)d_in[i]; break;
            default: break;
        }
    }
    float* out = (float*)d_out;

    cudaFuncSetAttribute(gemm_H_tf32_kernel,
                         cudaFuncAttributeMaxDynamicSharedMemorySize, GEMM_SMEM);
    cudaFuncSetAttribute(attn_mma_kernel,
                         cudaFuncAttributeMaxDynamicSharedMemorySize, SMEM_DYN);

    dim3 gH(NNODES / 128, FOUT / 64);
    gemm_H_tf32_kernel<<<gH, 256, GEMM_SMEM>>>(X, W);
    st_kernel<<<NNODES / 8, 256>>>(AW);
    attn_mma_kernel<<<NNODES / BM, ATTN_THREADS, SMEM_DYN>>>(M, out);
}